// round 12
// baseline (speedup 1.0000x reference)
#include <cuda_runtime.h>

// ChamferDistanceLoss via exact 1-D bucket-pruned NN.
// d2(q,p) = qn + (pn - 2 q.p); for each query, only points with
// (x_p - x_q)^2 <= best_d2 can win (d2 >= dx^2). Points are bucketed by x
// (256 buckets); window expands bucket-by-bucket outward until the bucket
// edge distance exceeds best (+ margin). Exact: bound is monotone, extra
// scanned points only confirm the min. PAD rows (coords=1e4) have pn~3e8 ->
// never win as refs; as queries they're detected and masked.
// R10 fix: the PAD-query substitution shfl is now executed by ALL lanes
// (subset-of-mask shfl was deadlocking the warp).

#define PADV   10000.0f
#define NB     256
#define XMIN   (-6.0f)
#define XW     (12.0f / NB)
#define INVW   (NB / 12.0f)
#define WMARGIN 1e-5f
#define MAXB   8
#define MAXQ   4096
#define RCHUNK 8

typedef unsigned long long u64;

// bucketed point data: [b][set][{-2x,-2y,-2z,pn}][i]
static __device__ float g_ref[MAXB][2][4][MAXQ];
static __device__ int   g_sidx[MAXB][2][MAXQ];   // original index of bucketed slot
static __device__ int   g_boff[MAXB][2][NB + 1]; // bucket offsets
static __device__ float g_min[2][MAXB][MAXQ];    // per-query min d2 (orig idx)
static __device__ float g_rsum[2][MAXB][RCHUNK];
static __device__ float g_rcnt[MAXB][RCHUNK];

__device__ __forceinline__ u64 ffma2(u64 a, u64 b, u64 c) {
    u64 d;
    asm("fma.rn.f32x2 %0, %1, %2, %3;" : "=l"(d) : "l"(a), "l"(b), "l"(c));
    return d;
}
__device__ __forceinline__ void unpack2(u64 v, float& lo, float& hi) {
    asm("mov.b64 {%0, %1}, %2;" : "=f"(lo), "=f"(hi) : "l"(v));
}
__device__ __forceinline__ u64 pack2(float lo, float hi) {
    u64 d;
    asm("mov.b64 %0, {%1, %2};" : "=l"(d) : "f"(lo), "f"(hi));
    return d;
}
__device__ __forceinline__ int bucket_of(float x) {
    float t = (x - XMIN) * INVW;
    t = fminf(fmaxf(t, 0.0f), (float)(NB - 1));   // clamp in float (avoid int UB on inf)
    return (int)t;
}

// One block per (set, b): histogram + prefix + scatter into g_ref/g_sidx.
__global__ __launch_bounds__(512) void bucket_kernel(const float* __restrict__ fg,
                                                     const float* __restrict__ prj,
                                                     int N, int M) {
    __shared__ int h[NB], off[NB + 1], cur[NB];
    int set = blockIdx.x, b = blockIdx.y;
    const float* pts = set ? prj : fg;
    int n = set ? M : N;

    for (int i = threadIdx.x; i < NB; i += blockDim.x) h[i] = 0;
    __syncthreads();
    for (int i = threadIdx.x; i < MAXQ; i += blockDim.x) {
        float x = (i < n) ? pts[((size_t)b * n + i) * 3] : 3.0e38f;
        atomicAdd(&h[bucket_of(x)], 1);
    }
    __syncthreads();
    if (threadIdx.x == 0) {
        int run = 0;
        for (int k = 0; k < NB; k++) { off[k] = run; run += h[k]; }
        off[NB] = run;   // == MAXQ
    }
    __syncthreads();
    for (int i = threadIdx.x; i < NB; i += blockDim.x) cur[i] = off[i];
    for (int i = threadIdx.x; i <= NB; i += blockDim.x) g_boff[b][set][i] = off[i];
    __syncthreads();
    for (int i = threadIdx.x; i < MAXQ; i += blockDim.x) {
        float x, y, z;
        if (i < n) {
            const float* p = pts + ((size_t)b * n + i) * 3;
            x = p[0]; y = p[1]; z = p[2];
        } else { x = 3.0e38f; y = 0.f; z = 0.f; }
        int k = bucket_of(x);
        int pos = atomicAdd(&cur[k], 1);
        g_ref[b][set][0][pos] = -2.f * x;
        g_ref[b][set][1][pos] = -2.f * y;
        g_ref[b][set][2][pos] = -2.f * z;
        g_ref[b][set][3][pos] = (i < n) ? (x*x + y*y + z*z) : 3.0e38f;
        g_sidx[b][set][pos] = (i < n) ? i : 0;
    }
}

// grid: (MAXQ/256, B, 2). Each warp: 32 x-adjacent queries, expanding bucket
// window over the opposite (staged) set. All intra-warp collectives are
// executed by all 32 lanes unconditionally.
__global__ __launch_bounds__(256) void window_kernel(int N, int M) {
    extern __shared__ float s[];
    float* s_m2x = s;
    float* s_m2y = s + MAXQ;
    float* s_m2z = s + 2 * MAXQ;
    float* s_pn  = s + 3 * MAXQ;
    int*   s_off = (int*)(s + 4 * MAXQ);

    int b = blockIdx.y, dir = blockIdx.z;
    int qset = dir ? 1 : 0;          // dir0: queries=fg(0), refs=prj(1)
    int rset = 1 - qset;
    int Nq = dir ? M : N;

    // stage refs (64KB) + bucket offsets
    {
        const float4* src = (const float4*)&g_ref[b][rset][0][0];
        float4* dst = (float4*)s;
        for (int i = threadIdx.x; i < MAXQ; i += blockDim.x) dst[i] = src[i];
        for (int i = threadIdx.x; i <= NB; i += blockDim.x) s_off[i] = g_boff[b][rset][i];
    }
    __syncthreads();

    int lane = threadIdx.x & 31;
    int qi = (blockIdx.x * (blockDim.x >> 5) + (threadIdx.x >> 5)) * 32 + lane;
    bool inrange = qi < Nq;
    int qc = inrange ? qi : 0;

    float qm2x = g_ref[b][qset][0][qc];
    float qm2y = g_ref[b][qset][1][qc];
    float qm2z = g_ref[b][qset][2][qc];
    float qn   = g_ref[b][qset][3][qc];
    float qx = -0.5f * qm2x;
    bool valid = inrange && (qx != PADV) && (qx < 1.0e37f);
    unsigned vmask = __ballot_sync(0xFFFFFFFFu, valid);
    if (vmask == 0) return;                 // warp-uniform: whole warp PAD/out
    int src_lane = __ffs(vmask) - 1;
    // substitute a valid lane's query into invalid lanes: ALL lanes shfl,
    // then select per-lane (subset-of-mask shfl deadlocks -- R9 bug).
    {
        float tx = __shfl_sync(0xFFFFFFFFu, qm2x, src_lane);
        float ty = __shfl_sync(0xFFFFFFFFu, qm2y, src_lane);
        float tz = __shfl_sync(0xFFFFFFFFu, qm2z, src_lane);
        float tn = __shfl_sync(0xFFFFFFFFu, qn,   src_lane);
        if (!valid) { qm2x = tx; qm2y = ty; qm2z = tz; qn = tn; qx = -0.5f * qm2x; }
    }
    float qy = -0.5f * qm2y, qz = -0.5f * qm2z;
    u64 q2x = pack2(qx, qx), q2y = pack2(qy, qy), q2z = pack2(qz, qz);

    int bq = bucket_of(qx);
    int start = (int)__reduce_min_sync(0xFFFFFFFFu, (unsigned)bq);
    int blo = start, bhi = start;           // scanned bucket range [blo, bhi)
    float best = 3.0e38f;                   // min of d' = pn - 2 q.p

    while (true) {
        bool nl = false, nr = false;
        if (blo > 0) {
            float xe = XMIN + blo * XW;     // unscanned left points have x < xe
            float dx = qx - xe;
            nl = (xe > qx) || (dx * dx <= best + qn + WMARGIN);
        }
        if (bhi < NB) {
            float xe = XMIN + bhi * XW;     // unscanned right points have x >= xe
            float dx = xe - qx;
            nr = (xe <= qx) || (dx * dx <= best + qn + WMARGIN);
        }
        bool anyl = __any_sync(0xFFFFFFFFu, nl);
        bool anyr = __any_sync(0xFFFFFFFFu, nr);
        if (!anyl && !anyr) break;
        int c0, c1;
        if (anyr) { c0 = s_off[bhi]; c1 = s_off[bhi + 1]; bhi++; }
        else      { blo--; c0 = s_off[blo]; c1 = s_off[blo + 1]; }
        // pair-align; over-scan is safe (extra real points can't beat true min)
        c0 &= ~1;
        c1 = min((c1 + 1) & ~1, MAXQ);
        for (int jj = c0; jj < c1; jj += 2) {
            u64 px = *(const u64*)&s_m2x[jj];
            u64 py = *(const u64*)&s_m2y[jj];
            u64 pz = *(const u64*)&s_m2z[jj];
            u64 pw = *(const u64*)&s_pn[jj];
            u64 d = ffma2(pz, q2z, pw);
            d = ffma2(py, q2y, d);
            d = ffma2(px, q2x, d);
            float l, h;
            unpack2(d, l, h);
            best = fminf(best, fminf(l, h));
        }
    }
    if (valid) g_min[dir][b][g_sidx[b][qset][qi]] = best + qn;
}

// grid: (RCHUNK, B, 2). dir0: masked sum + count over valid fg; dir1: sum.
__global__ __launch_bounds__(256) void reduce_kernel(const float* __restrict__ fg,
                                                     int N, int M) {
    const int RT = 256;
    int chunk = blockIdx.x, b = blockIdx.y, dir = blockIdx.z;
    int Nq  = dir ? M : N;
    int per = (Nq + RCHUNK - 1) / RCHUNK;
    int qs  = chunk * per;
    int qe  = min(qs + per, Nq);

    float sum = 0.f, cntv = 0.f;
    for (int qi = qs + threadIdx.x; qi < qe; qi += RT) {
        if (dir == 0) {
            if (fg[((size_t)b * N + qi) * 3] != PADV) {
                sum += fmaxf(g_min[0][b][qi], 0.f);
                cntv += 1.f;
            }
        } else {
            sum += fmaxf(g_min[1][b][qi], 0.f);
        }
    }
    #pragma unroll
    for (int o = 16; o > 0; o >>= 1) {
        sum  += __shfl_xor_sync(0xFFFFFFFFu, sum,  o);
        cntv += __shfl_xor_sync(0xFFFFFFFFu, cntv, o);
    }
    __shared__ float ws[RT / 32][2];
    int wid = threadIdx.x / 32, lane2 = threadIdx.x % 32;
    if (lane2 == 0) { ws[wid][0] = sum; ws[wid][1] = cntv; }
    __syncthreads();
    if (threadIdx.x == 0) {
        float ts = 0.f, tc = 0.f;
        for (int w = 0; w < RT / 32; w++) { ts += ws[w][0]; tc += ws[w][1]; }
        g_rsum[dir][b][chunk] = ts;
        if (dir == 0) g_rcnt[b][chunk] = tc;
    }
}

__global__ void final_kernel(float* out, int M, int B) {
    float v = 0.f;
    if (threadIdx.x < B) {
        int b = threadIdx.x;
        float sx = 0.f, sy = 0.f, c = 0.f;
        #pragma unroll
        for (int ch = 0; ch < RCHUNK; ch++) {
            sx += g_rsum[0][b][ch];
            sy += g_rsum[1][b][ch];
            c  += g_rcnt[b][ch];
        }
        v = sx / c + sy / (float)M;
    }
    #pragma unroll
    for (int o = 16; o > 0; o >>= 1) v += __shfl_xor_sync(0xFFFFFFFFu, v, o);
    if (threadIdx.x == 0) out[0] = v / (float)B;
}

extern "C" void kernel_launch(void* const* d_in, const int* in_sizes, int n_in,
                              void* d_out, int out_size) {
    const float* fg  = (const float*)d_in[0];
    const float* prj = (const float*)d_in[1];
    int B = in_sizes[2];
    int N = in_sizes[0] / (3 * B);
    int M = in_sizes[1] / (3 * B);
    float* out = (float*)d_out;

    int smem_bytes = 4 * MAXQ * 4 + (NB + 1) * 4;   // 64KB refs + offsets
    cudaFuncSetAttribute(window_kernel,
                         cudaFuncAttributeMaxDynamicSharedMemorySize, smem_bytes);

    bucket_kernel<<<dim3(2, B), 512>>>(fg, prj, N, M);
    int maxq = (N > M) ? N : M;
    int xblocks = (maxq + 255) / 256;               // 16 for 4096
    window_kernel<<<dim3(xblocks, B, 2), 256, smem_bytes>>>(N, M);
    reduce_kernel<<<dim3(RCHUNK, B, 2), 256>>>(fg, N, M);
    final_kernel<<<1, 32>>>(out, M, B);
}

// round 13
// speedup vs baseline: 1.0987x; 1.0987x over previous
#include <cuda_runtime.h>

// ChamferDistanceLoss via exact 1-D bucket-pruned NN (3 launches).
// d2 >= (dx)^2, so only points with |x_p - x_q| <= sqrt(best_d2) can win.
// Points bucketed by x (256 buckets), stored PAIR-INTERLEAVED for f32x2.
// Window kernel: seed best from the warp's own neighborhood (>=64 pts),
// then one tight scan over the exact warp-union x-window. Over-scan is
// always safe (extra real points only confirm the min). PAD rows have
// pn=3e38 as refs (never win); PAD queries are substituted+masked.

#define PADV   10000.0f
#define NB     256
#define XMIN   (-6.0f)
#define XW     (12.0f / NB)
#define INVW   (NB / 12.0f)
#define MAXB   8
#define MAXQ   4096
#define NPAIR  (MAXQ / 2)

typedef unsigned long long u64;

// pair-interleaved bucketed refs: [b][set][pair][{x0,x1,y0,y1,z0,z1,w0,w1}]
// components store (-2x, -2y, -2z, ||p||^2)
static __device__ float g_pair[MAXB][2][NPAIR][8];
static __device__ int   g_sidx[MAXB][2][MAXQ];   // bucketed slot -> original index
static __device__ int   g_boff[MAXB][2][NB + 1];
static __device__ float g_min[2][MAXB][MAXQ];    // per-query min d2, original index

__device__ __forceinline__ u64 ffma2(u64 a, u64 b, u64 c) {
    u64 d;
    asm("fma.rn.f32x2 %0, %1, %2, %3;" : "=l"(d) : "l"(a), "l"(b), "l"(c));
    return d;
}
__device__ __forceinline__ void unpack2(u64 v, float& lo, float& hi) {
    asm("mov.b64 {%0, %1}, %2;" : "=f"(lo), "=f"(hi) : "l"(v));
}
__device__ __forceinline__ u64 pack2(float lo, float hi) {
    u64 d;
    asm("mov.b64 %0, {%1, %2};" : "=l"(d) : "f"(lo), "f"(hi));
    return d;
}
__device__ __forceinline__ int bucket_of(float x) {
    float t = (x - XMIN) * INVW;
    t = fminf(fmaxf(t, 0.0f), (float)(NB - 1));
    return (int)t;
}

// One block per (set, b): histogram + warp-parallel prefix + scatter.
__global__ __launch_bounds__(512) void bucket_kernel(const float* __restrict__ fg,
                                                     const float* __restrict__ prj,
                                                     float* out, int N, int M) {
    __shared__ int h[NB], off[NB + 1], cur[NB];
    int set = blockIdx.x, b = blockIdx.y;
    if (set == 0 && b == 0 && threadIdx.x == 0) out[0] = 0.0f;  // zero accumulator
    const float* pts = set ? prj : fg;
    int n = set ? M : N;

    for (int i = threadIdx.x; i < NB; i += blockDim.x) h[i] = 0;
    __syncthreads();
    for (int i = threadIdx.x; i < MAXQ; i += blockDim.x) {
        float x = (i < n) ? pts[((size_t)b * n + i) * 3] : 3.0e38f;
        atomicAdd(&h[bucket_of(x)], 1);
    }
    __syncthreads();
    // warp 0: parallel exclusive prefix over 256 buckets (8 per lane)
    if (threadIdx.x < 32) {
        int lane = threadIdx.x;
        int v[8], lsum = 0;
        #pragma unroll
        for (int k = 0; k < 8; k++) { v[k] = h[lane * 8 + k]; lsum += v[k]; }
        int excl = lsum;
        #pragma unroll
        for (int o = 1; o < 32; o <<= 1) {
            int t = __shfl_up_sync(0xFFFFFFFFu, excl, o);
            if (lane >= o) excl += t;
        }
        excl -= lsum;   // exclusive
        int run = excl;
        #pragma unroll
        for (int k = 0; k < 8; k++) { off[lane * 8 + k] = run; run += v[k]; }
        if (lane == 31) off[NB] = run;
    }
    __syncthreads();
    for (int i = threadIdx.x; i < NB; i += blockDim.x) cur[i] = off[i];
    for (int i = threadIdx.x; i <= NB; i += blockDim.x) g_boff[b][set][i] = off[i];
    __syncthreads();
    for (int i = threadIdx.x; i < MAXQ; i += blockDim.x) {
        float x, y, z;
        if (i < n) {
            const float* p = pts + ((size_t)b * n + i) * 3;
            x = p[0]; y = p[1]; z = p[2];
        } else { x = 3.0e38f; y = 0.f; z = 0.f; }
        int k = bucket_of(x);
        int pos = atomicAdd(&cur[k], 1);
        int pr = pos >> 1, ln = pos & 1;
        g_pair[b][set][pr][0 + ln] = -2.f * x;
        g_pair[b][set][pr][2 + ln] = -2.f * y;
        g_pair[b][set][pr][4 + ln] = -2.f * z;
        g_pair[b][set][pr][6 + ln] = (i < n) ? (x*x + y*y + z*z) : 3.0e38f;
        g_sidx[b][set][pos] = (i < n) ? i : 0;
    }
}

// grid: (MAXQ/256, B, 2), 256 threads. Warp = 32 x-adjacent bucketed queries.
__global__ __launch_bounds__(256) void window_kernel(int N, int M) {
    extern __shared__ char smem[];
    u64 (*s_pair)[4] = (u64 (*)[4])smem;                 // 64KB
    int* s_off = (int*)(smem + NPAIR * 4 * sizeof(u64)); // 1KB+

    int b = blockIdx.y, dir = blockIdx.z;
    int qset = dir ? 1 : 0;          // dir0: queries=fg(0), refs=prj(1)
    int rset = 1 - qset;
    int Nq = dir ? M : N;

    {   // stage refs + offsets
        const float4* src = (const float4*)&g_pair[b][rset][0][0];
        float4* dst = (float4*)smem;
        for (int i = threadIdx.x; i < NPAIR * 2; i += blockDim.x) dst[i] = src[i];
        for (int i = threadIdx.x; i <= NB; i += blockDim.x) s_off[i] = g_boff[b][rset][i];
    }
    __syncthreads();

    int lane = threadIdx.x & 31;
    int qi = (blockIdx.x * (blockDim.x >> 5) + (threadIdx.x >> 5)) * 32 + lane;
    bool inrange = qi < Nq;
    int qc = inrange ? qi : 0;
    int pr = qc >> 1, ln = qc & 1;
    float qm2x = g_pair[b][qset][pr][0 + ln];
    float qm2y = g_pair[b][qset][pr][2 + ln];
    float qm2z = g_pair[b][qset][pr][4 + ln];
    float qn   = g_pair[b][qset][pr][6 + ln];
    float qx = -0.5f * qm2x;
    bool valid = inrange && (qx != PADV) && (qx < 1.0e37f);
    unsigned vmask = __ballot_sync(0xFFFFFFFFu, valid);
    if (vmask == 0) return;                 // warp-uniform (no barriers follow)
    int src_lane = __ffs(vmask) - 1;
    {   // substitute valid query into invalid lanes (ALL lanes shfl)
        float tx = __shfl_sync(0xFFFFFFFFu, qm2x, src_lane);
        float ty = __shfl_sync(0xFFFFFFFFu, qm2y, src_lane);
        float tz = __shfl_sync(0xFFFFFFFFu, qm2z, src_lane);
        float tn = __shfl_sync(0xFFFFFFFFu, qn,   src_lane);
        if (!valid) { qm2x = tx; qm2y = ty; qm2z = tz; qn = tn; qx = -0.5f * qm2x; }
    }
    u64 q2x = pack2(-0.5f * qm2x, -0.5f * qm2x);  // (qx,qx) -- refs carry the -2
    u64 q2y = pack2(-0.5f * qm2y, -0.5f * qm2y);
    u64 q2z = pack2(-0.5f * qm2z, -0.5f * qm2z);

    int bq = bucket_of(qx);
    int bqlo = (int)__reduce_min_sync(0xFFFFFFFFu, (unsigned)bq);
    int bqhi = (int)__reduce_max_sync(0xFFFFFFFFu, (unsigned)bq);

    float best = 3.0e38f;   // running min of d' = pn - 2 q.p

    // ---- phase A: seed from neighborhood, widened by index to >= 64 pts ----
    {
        int c0 = s_off[max(bqlo - 1, 0)];
        int c1 = s_off[min(bqhi + 2, NB)];
        int need = 64 - (c1 - c0);
        if (need > 0) { c0 = max(0, c0 - need); c1 = min(MAXQ, c1 + need); }
        int j0 = c0 >> 1, j1 = (c1 + 1) >> 1;
        for (int j = j0; j < j1; j++) {
            ulonglong2 xy = *(const ulonglong2*)&s_pair[j][0];
            ulonglong2 zw = *(const ulonglong2*)&s_pair[j][2];
            u64 d = ffma2(zw.x, q2z, zw.y);
            d = ffma2(xy.y, q2y, d);
            d = ffma2(xy.x, q2x, d);
            float l, h;
            unpack2(d, l, h);
            best = fminf(best, fminf(l, h));
        }
    }

    // ---- phase B: exact window scan ----
    {
        float r = sqrtf(fmaxf(best + qn, 0.f) + 1e-5f) + XW;  // conservative
        int blo = bucket_of(qx - r), bhi = bucket_of(qx + r);
        blo = (int)__reduce_min_sync(0xFFFFFFFFu, (unsigned)blo);
        bhi = (int)__reduce_max_sync(0xFFFFFFFFu, (unsigned)bhi);
        int w0 = s_off[blo], w1 = s_off[bhi + 1];
        int j0 = w0 >> 1, j1 = (w1 + 1) >> 1;
        for (int j = j0; j < j1; j++) {
            ulonglong2 xy = *(const ulonglong2*)&s_pair[j][0];
            ulonglong2 zw = *(const ulonglong2*)&s_pair[j][2];
            u64 d = ffma2(zw.x, q2z, zw.y);
            d = ffma2(xy.y, q2y, d);
            d = ffma2(xy.x, q2x, d);
            float l, h;
            unpack2(d, l, h);
            best = fminf(best, fminf(l, h));
        }
    }
    if (valid) g_min[dir][b][g_sidx[b][qset][qi]] = best + qn;
}

// grid: (B). Per-sample sums for both directions + atomicAdd into out.
__global__ __launch_bounds__(256) void reduce_final(const float* __restrict__ fg,
                                                    float* out, int N, int M, int B) {
    const int RT = 256;
    int b = blockIdx.x;
    float sx = 0.f, sy = 0.f, cv = 0.f;
    for (int i = threadIdx.x; i < N; i += RT) {
        if (fg[((size_t)b * N + i) * 3] != PADV) {
            sx += fmaxf(g_min[0][b][i], 0.f);
            cv += 1.f;
        }
    }
    for (int i = threadIdx.x; i < M; i += RT)
        sy += fmaxf(g_min[1][b][i], 0.f);

    #pragma unroll
    for (int o = 16; o > 0; o >>= 1) {
        sx += __shfl_xor_sync(0xFFFFFFFFu, sx, o);
        sy += __shfl_xor_sync(0xFFFFFFFFu, sy, o);
        cv += __shfl_xor_sync(0xFFFFFFFFu, cv, o);
    }
    __shared__ float ws[RT / 32][3];
    int wid = threadIdx.x / 32, lane = threadIdx.x % 32;
    if (lane == 0) { ws[wid][0] = sx; ws[wid][1] = sy; ws[wid][2] = cv; }
    __syncthreads();
    if (threadIdx.x == 0) {
        float tsx = 0.f, tsy = 0.f, tc = 0.f;
        for (int w = 0; w < RT / 32; w++) {
            tsx += ws[w][0]; tsy += ws[w][1]; tc += ws[w][2];
        }
        atomicAdd(out, (tsx / tc + tsy / (float)M) / (float)B);
    }
}

extern "C" void kernel_launch(void* const* d_in, const int* in_sizes, int n_in,
                              void* d_out, int out_size) {
    const float* fg  = (const float*)d_in[0];
    const float* prj = (const float*)d_in[1];
    int B = in_sizes[2];
    int N = in_sizes[0] / (3 * B);
    int M = in_sizes[1] / (3 * B);
    float* out = (float*)d_out;

    int smem_bytes = NPAIR * 4 * sizeof(u64) + (NB + 1) * sizeof(int);  // ~65.5KB
    cudaFuncSetAttribute(window_kernel,
                         cudaFuncAttributeMaxDynamicSharedMemorySize, smem_bytes);

    bucket_kernel<<<dim3(2, B), 512>>>(fg, prj, out, N, M);
    int maxq = (N > M) ? N : M;
    int xblocks = (maxq + 255) / 256;               // 16 for 4096
    window_kernel<<<dim3(xblocks, B, 2), 256, smem_bytes>>>(N, M);
    reduce_final<<<B, 256>>>(fg, out, N, M, B);
}

// round 14
// speedup vs baseline: 1.4331x; 1.3044x over previous
#include <cuda_runtime.h>

// ChamferDistanceLoss via exact 1-D bucket-pruned NN (3 launches).
// d2 >= (dx)^2: only points with |x_p - x_q| <= sqrt(best_d2) can win.
// Bucketed by x (256 buckets); refs stored as float4 {-2x,-2y,-2z,||p||^2};
// window kernel stages+pair-transposes refs into smem, seeds best from the
// 128 x-nearest (by sorted index), then scans the exact warp-union window
// with an unrolled f32x2 FFMA loop. Over-scan only confirms the min (exact).
// PAD rows: pn=3e38 as refs (never win); PAD queries substituted + masked.

#define PADV   10000.0f
#define NB     256
#define XMIN   (-6.0f)
#define XW     (12.0f / NB)
#define INVW   (NB / 12.0f)
#define MAXB   8
#define MAXQ   4096
#define NPAIR  (MAXQ / 2)

typedef unsigned long long u64;

static __device__ float4 g_ref4[MAXB][2][MAXQ];  // bucketed: {-2x,-2y,-2z,pn}
static __device__ int    g_sidx[MAXB][2][MAXQ];  // bucketed slot -> original index
static __device__ int    g_boff[MAXB][2][NB + 1];
static __device__ float  g_min[2][MAXB][MAXQ];   // per-query min d2, original index

__device__ __forceinline__ u64 ffma2(u64 a, u64 b, u64 c) {
    u64 d;
    asm("fma.rn.f32x2 %0, %1, %2, %3;" : "=l"(d) : "l"(a), "l"(b), "l"(c));
    return d;
}
__device__ __forceinline__ void unpack2(u64 v, float& lo, float& hi) {
    asm("mov.b64 {%0, %1}, %2;" : "=f"(lo), "=f"(hi) : "l"(v));
}
__device__ __forceinline__ u64 pack2(float lo, float hi) {
    u64 d;
    asm("mov.b64 %0, {%1, %2};" : "=l"(d) : "f"(lo), "f"(hi));
    return d;
}
__device__ __forceinline__ int bucket_of(float x) {
    float t = (x - XMIN) * INVW;
    t = fminf(fmaxf(t, 0.0f), (float)(NB - 1));
    return (int)t;
}

// One block per (set, b), 1024 threads: histogram + warp prefix + scatter
// (one STG.128 + one STG.32 per point).
__global__ __launch_bounds__(1024) void bucket_kernel(const float* __restrict__ fg,
                                                      const float* __restrict__ prj,
                                                      float* out, int N, int M) {
    __shared__ int h[NB], off[NB + 1], cur[NB];
    int set = blockIdx.x, b = blockIdx.y;
    if (set == 0 && b == 0 && threadIdx.x == 0) out[0] = 0.0f;
    const float* pts = set ? prj : fg;
    int n = set ? M : N;

    for (int i = threadIdx.x; i < NB; i += blockDim.x) h[i] = 0;
    __syncthreads();
    for (int i = threadIdx.x; i < MAXQ; i += blockDim.x) {
        float x = (i < n) ? __ldg(&pts[((size_t)b * n + i) * 3]) : 3.0e38f;
        atomicAdd(&h[bucket_of(x)], 1);
    }
    __syncthreads();
    if (threadIdx.x < 32) {   // warp 0: exclusive prefix over 256 buckets
        int lane = threadIdx.x;
        int v[8], lsum = 0;
        #pragma unroll
        for (int k = 0; k < 8; k++) { v[k] = h[lane * 8 + k]; lsum += v[k]; }
        int excl = lsum;
        #pragma unroll
        for (int o = 1; o < 32; o <<= 1) {
            int t = __shfl_up_sync(0xFFFFFFFFu, excl, o);
            if (lane >= o) excl += t;
        }
        excl -= lsum;
        int run = excl;
        #pragma unroll
        for (int k = 0; k < 8; k++) { off[lane * 8 + k] = run; run += v[k]; }
        if (lane == 31) off[NB] = run;
    }
    __syncthreads();
    for (int i = threadIdx.x; i < NB; i += blockDim.x) cur[i] = off[i];
    for (int i = threadIdx.x; i <= NB; i += blockDim.x) g_boff[b][set][i] = off[i];
    __syncthreads();
    for (int i = threadIdx.x; i < MAXQ; i += blockDim.x) {
        float x, y, z, w;
        if (i < n) {
            const float* p = pts + ((size_t)b * n + i) * 3;
            x = __ldg(&p[0]); y = __ldg(&p[1]); z = __ldg(&p[2]);
            w = x * x + y * y + z * z;
        } else { x = 3.0e38f; y = 0.f; z = 0.f; w = 3.0e38f; }
        int pos = atomicAdd(&cur[bucket_of(x)], 1);
        g_ref4[b][set][pos] = make_float4(-2.f * x, -2.f * y, -2.f * z, w);
        g_sidx[b][set][pos] = (i < n) ? i : 0;
    }
}

// grid: (MAXQ/256, B, 2), 256 threads. Warp = 32 x-adjacent bucketed queries.
__global__ __launch_bounds__(256) void window_kernel(int N, int M) {
    extern __shared__ char smem[];
    u64 (*s_pair)[4] = (u64 (*)[4])smem;                 // 64KB pair-interleaved
    float* sp = (float*)smem;
    int* s_off = (int*)(smem + NPAIR * 4 * sizeof(u64));

    int b = blockIdx.y, dir = blockIdx.z;
    int qset = dir ? 1 : 0;          // dir0: queries=fg(0), refs=prj(1)
    int rset = 1 - qset;
    int Nq = dir ? M : N;

    // stage refs with pair-transpose: slot s -> pair s>>1, lane-half s&1
    for (int s = threadIdx.x; s < MAXQ; s += blockDim.x) {
        float4 v = g_ref4[b][rset][s];
        int j = s >> 1, ln = s & 1;
        sp[j * 8 + 0 + ln] = v.x;
        sp[j * 8 + 2 + ln] = v.y;
        sp[j * 8 + 4 + ln] = v.z;
        sp[j * 8 + 6 + ln] = v.w;
    }
    for (int i = threadIdx.x; i <= NB; i += blockDim.x) s_off[i] = g_boff[b][rset][i];
    __syncthreads();

    int lane = threadIdx.x & 31;
    int qi = (blockIdx.x * (blockDim.x >> 5) + (threadIdx.x >> 5)) * 32 + lane;
    bool inrange = qi < Nq;
    int qc = inrange ? qi : 0;
    float4 qv = g_ref4[b][qset][qc];
    float qx = -0.5f * qv.x, qy = -0.5f * qv.y, qz = -0.5f * qv.z, qn = qv.w;
    bool valid = inrange && (qx != PADV) && (qx < 1.0e37f);
    unsigned vmask = __ballot_sync(0xFFFFFFFFu, valid);
    if (vmask == 0) return;                 // warp-uniform; no barriers follow
    int src_lane = __ffs(vmask) - 1;
    {   // substitute a valid lane's query into invalid lanes (ALL lanes shfl)
        float tx = __shfl_sync(0xFFFFFFFFu, qx, src_lane);
        float ty = __shfl_sync(0xFFFFFFFFu, qy, src_lane);
        float tz = __shfl_sync(0xFFFFFFFFu, qz, src_lane);
        float tn = __shfl_sync(0xFFFFFFFFu, qn, src_lane);
        if (!valid) { qx = tx; qy = ty; qz = tz; qn = tn; }
    }
    u64 q2x = pack2(qx, qx), q2y = pack2(qy, qy), q2z = pack2(qz, qz);

    int bq = bucket_of(qx);
    int bqlo = (int)__reduce_min_sync(0xFFFFFFFFu, (unsigned)bq);
    int bqhi = (int)__reduce_max_sync(0xFFFFFFFFu, (unsigned)bq);

    float best = 3.0e38f;   // running min of d' = pn - 2 q.p

    // ---- phase A: seed from 128 x-nearest by sorted index (warp-uniform) ----
    {
        int center = (s_off[bqlo] + s_off[bqhi + 1]) >> 1;
        int c0 = max(center - 64, 0);
        int c1 = min(center + 64, MAXQ);
        int j0 = c0 >> 1, j1 = (c1 + 1) >> 1;
        #pragma unroll 4
        for (int j = j0; j < j1; j++) {
            ulonglong2 xy = *(const ulonglong2*)&s_pair[j][0];
            ulonglong2 zw = *(const ulonglong2*)&s_pair[j][2];
            u64 d = ffma2(zw.x, q2z, zw.y);
            d = ffma2(xy.y, q2y, d);
            d = ffma2(xy.x, q2x, d);
            float l, h;
            unpack2(d, l, h);
            best = fminf(best, fminf(l, h));
        }
    }

    // ---- phase B: exact window scan ----
    {
        float r = sqrtf(fmaxf(best + qn, 0.f) + 1e-4f) + 2e-3f;  // conservative
        int blo = bucket_of(qx - r), bhi = bucket_of(qx + r);
        blo = (int)__reduce_min_sync(0xFFFFFFFFu, (unsigned)blo);
        bhi = (int)__reduce_max_sync(0xFFFFFFFFu, (unsigned)bhi);
        int w0 = s_off[blo], w1 = s_off[bhi + 1];
        int j0 = w0 >> 1, j1 = (w1 + 1) >> 1;
        #pragma unroll 4
        for (int j = j0; j < j1; j++) {
            ulonglong2 xy = *(const ulonglong2*)&s_pair[j][0];
            ulonglong2 zw = *(const ulonglong2*)&s_pair[j][2];
            u64 d = ffma2(zw.x, q2z, zw.y);
            d = ffma2(xy.y, q2y, d);
            d = ffma2(xy.x, q2x, d);
            float l, h;
            unpack2(d, l, h);
            best = fminf(best, fminf(l, h));
        }
    }
    if (valid) g_min[dir][b][g_sidx[b][qset][qi]] = best + qn;
}

// grid: (B). Per-sample sums for both directions + atomicAdd into out.
__global__ __launch_bounds__(256) void reduce_final(const float* __restrict__ fg,
                                                    float* out, int N, int M, int B) {
    const int RT = 256;
    int b = blockIdx.x;
    float sx = 0.f, sy = 0.f, cv = 0.f;
    for (int i = threadIdx.x; i < N; i += RT) {
        if (fg[((size_t)b * N + i) * 3] != PADV) {
            sx += fmaxf(g_min[0][b][i], 0.f);
            cv += 1.f;
        }
    }
    for (int i = threadIdx.x; i < M; i += RT)
        sy += fmaxf(g_min[1][b][i], 0.f);

    #pragma unroll
    for (int o = 16; o > 0; o >>= 1) {
        sx += __shfl_xor_sync(0xFFFFFFFFu, sx, o);
        sy += __shfl_xor_sync(0xFFFFFFFFu, sy, o);
        cv += __shfl_xor_sync(0xFFFFFFFFu, cv, o);
    }
    __shared__ float ws[RT / 32][3];
    int wid = threadIdx.x / 32, lane = threadIdx.x % 32;
    if (lane == 0) { ws[wid][0] = sx; ws[wid][1] = sy; ws[wid][2] = cv; }
    __syncthreads();
    if (threadIdx.x == 0) {
        float tsx = 0.f, tsy = 0.f, tc = 0.f;
        for (int w = 0; w < RT / 32; w++) {
            tsx += ws[w][0]; tsy += ws[w][1]; tc += ws[w][2];
        }
        atomicAdd(out, (tsx / tc + tsy / (float)M) / (float)B);
    }
}

extern "C" void kernel_launch(void* const* d_in, const int* in_sizes, int n_in,
                              void* d_out, int out_size) {
    const float* fg  = (const float*)d_in[0];
    const float* prj = (const float*)d_in[1];
    int B = in_sizes[2];
    int N = in_sizes[0] / (3 * B);
    int M = in_sizes[1] / (3 * B);
    float* out = (float*)d_out;

    int smem_bytes = NPAIR * 4 * sizeof(u64) + (NB + 1) * sizeof(int);  // ~65.5KB
    cudaFuncSetAttribute(window_kernel,
                         cudaFuncAttributeMaxDynamicSharedMemorySize, smem_bytes);

    bucket_kernel<<<dim3(2, B), 1024>>>(fg, prj, out, N, M);
    int maxq = (N > M) ? N : M;
    int xblocks = (maxq + 255) / 256;               // 16 for 4096
    window_kernel<<<dim3(xblocks, B, 2), 256, smem_bytes>>>(N, M);
    reduce_final<<<B, 256>>>(fg, out, N, M, B);
}